// round 14
// baseline (speedup 1.0000x reference)
#include <cuda_runtime.h>
#include <cuda_fp16.h>
#include <cuda.h>
#include <dlfcn.h>
#include <cstdint>
#include <cstdio>
#include <math.h>

#define DIM   1024
#define NH    16
#define HD    64
#define BATCH 4
#define SEQ   2048
#define CSC   0.18033688011112042f   /* 64^-0.5 * log2(e) */

#define MROWS (BATCH * SEQ)          /* 8192 */

__device__ __half g_x_h   [(size_t)MROWS * DIM];      // reused as f16 out-proj result
__device__ __half g_wqkv_h[(size_t)3 * DIM * DIM];    // [N][K]
__device__ __half g_wout_h[(size_t)DIM * DIM];        // [N][K]
__device__ __half g_qkv_h [(size_t)MROWS * 3 * DIM];
__device__ __half g_attn_h[(size_t)MROWS * DIM];

// ===========================================================================
// Hand-written PTX, JIT-compiled at runtime with .target sm_103a to unlock
// tcgen05. gemm_t5: C[M,N](f16) = A[M,K](f16) @ Bt[N,K](f16)^T, f32 TMEM accum.
// ===========================================================================
static const char* PTX_SRC = R"PTX(
.version 8.8
.target sm_103a
.address_size 64

.visible .entry gemm_t5(
    .param .u64 pA,
    .param .u64 pB,
    .param .u64 pC,
    .param .u32 pN,
    .param .u32 pK
)
{
    .reg .pred %p<12>;
    .reg .b32 %r<100>;
    .reg .f32 %f<40>;
    .reg .b64 %rd<40>;
    .shared .align 1024 .b8 dsm[33792];

    mov.u32 %r1, %tid.x;
    mov.u32 %r2, %ctaid.x;
    mov.u32 %r3, %ctaid.y;
    mov.u32 %r4, dsm;

    ld.param.u64 %rd1, [pA];
    ld.param.u64 %rd2, [pB];
    ld.param.u64 %rd4, [pC];
    ld.param.u32 %r5, [pN];
    ld.param.u32 %r6, [pK];
    cvta.to.global.u64 %rd1, %rd1;
    cvta.to.global.u64 %rd2, %rd2;
    cvta.to.global.u64 %rd4, %rd4;

    shr.u32 %r8, %r1, 5;
    setp.eq.u32 %p1, %r8, 0;
    add.u32 %r9, %r4, 8;
    @!%p1 bra SKIPA;
    tcgen05.alloc.cta_group::1.sync.aligned.shared::cta.b32 [%r4], 128;
    tcgen05.relinquish_alloc_permit.cta_group::1.sync.aligned;
SKIPA:
    setp.eq.u32 %p2, %r1, 0;
    @%p2 mbarrier.init.shared.b64 [%r9], 1;
    bar.sync 0;
    ld.shared.b32 %r10, [%r4];

    and.b32 %r11, %r1, 7;
    shl.b32 %r13, %r1, 7;
    add.u32 %r13, %r13, %r4;
    add.u32 %r13, %r13, 1024;
    shl.b32 %r14, %r11, 4;
    add.u32 %r20, %r13, %r14;
    xor.b32 %r14, %r11, 1; shl.b32 %r14, %r14, 4; add.u32 %r21, %r13, %r14;
    xor.b32 %r14, %r11, 2; shl.b32 %r14, %r14, 4; add.u32 %r22, %r13, %r14;
    xor.b32 %r14, %r11, 3; shl.b32 %r14, %r14, 4; add.u32 %r23, %r13, %r14;
    xor.b32 %r14, %r11, 4; shl.b32 %r14, %r14, 4; add.u32 %r24, %r13, %r14;
    xor.b32 %r14, %r11, 5; shl.b32 %r14, %r14, 4; add.u32 %r25, %r13, %r14;
    xor.b32 %r14, %r11, 6; shl.b32 %r14, %r14, 4; add.u32 %r26, %r13, %r14;
    xor.b32 %r14, %r11, 7; shl.b32 %r14, %r14, 4; add.u32 %r27, %r13, %r14;

    mad.lo.u32 %r15, %r3, 128, %r1;
    mul.wide.u32 %rd5, %r15, %r6;
    shl.b64 %rd5, %rd5, 1;
    add.s64 %rd5, %rd1, %rd5;
    mad.lo.u32 %r16, %r2, 128, %r1;
    mul.wide.u32 %rd6, %r16, %r6;
    shl.b64 %rd6, %rd6, 1;
    add.s64 %rd6, %rd2, %rd6;

    add.u32 %r30, %r4, 1024;
    shr.u32 %r31, %r30, 4;
    and.b32 %r31, %r31, 16383;
    cvt.u64.u32 %rd10, %r31;
    mov.u64 %rd11, 0x4000004000010000;
    or.b64 %rd10, %rd10, %rd11;
    add.u32 %r32, %r30, 16384;
    shr.u32 %r31, %r32, 4;
    and.b32 %r31, %r31, 16383;
    cvt.u64.u32 %rd12, %r31;
    or.b64 %rd12, %rd12, %rd11;
    mov.u32 %r33, 0x08200010;
    mov.u32 %r34, 0;
    shr.u32 %r28, %r6, 6;
    mov.u32 %r17, 0;

KLOOP:
    cp.async.cg.shared.global [%r20], [%rd5], 16;
    cp.async.cg.shared.global [%r21], [%rd5+16], 16;
    cp.async.cg.shared.global [%r22], [%rd5+32], 16;
    cp.async.cg.shared.global [%r23], [%rd5+48], 16;
    cp.async.cg.shared.global [%r24], [%rd5+64], 16;
    cp.async.cg.shared.global [%r25], [%rd5+80], 16;
    cp.async.cg.shared.global [%r26], [%rd5+96], 16;
    cp.async.cg.shared.global [%r27], [%rd5+112], 16;
    cp.async.cg.shared.global [%r20+16384], [%rd6], 16;
    cp.async.cg.shared.global [%r21+16384], [%rd6+16], 16;
    cp.async.cg.shared.global [%r22+16384], [%rd6+32], 16;
    cp.async.cg.shared.global [%r23+16384], [%rd6+48], 16;
    cp.async.cg.shared.global [%r24+16384], [%rd6+64], 16;
    cp.async.cg.shared.global [%r25+16384], [%rd6+80], 16;
    cp.async.cg.shared.global [%r26+16384], [%rd6+96], 16;
    cp.async.cg.shared.global [%r27+16384], [%rd6+112], 16;
    cp.async.commit_group;
    cp.async.wait_group 0;
    bar.sync 0;
    @!%p2 bra MMADONE;
    fence.proxy.async.shared::cta;
    setp.ne.u32 %p3, %r17, 0;
    tcgen05.mma.cta_group::1.kind::f16 [%r10], %rd10, %rd12, %r33, {%r34, %r34, %r34, %r34}, %p3;
    setp.eq.u32 %p5, %r34, 0;
    add.s64 %rd13, %rd10, 2;
    add.s64 %rd14, %rd12, 2;
    tcgen05.mma.cta_group::1.kind::f16 [%r10], %rd13, %rd14, %r33, {%r34, %r34, %r34, %r34}, %p5;
    add.s64 %rd13, %rd10, 4;
    add.s64 %rd14, %rd12, 4;
    tcgen05.mma.cta_group::1.kind::f16 [%r10], %rd13, %rd14, %r33, {%r34, %r34, %r34, %r34}, %p5;
    add.s64 %rd13, %rd10, 6;
    add.s64 %rd14, %rd12, 6;
    tcgen05.mma.cta_group::1.kind::f16 [%r10], %rd13, %rd14, %r33, {%r34, %r34, %r34, %r34}, %p5;
    tcgen05.commit.cta_group::1.mbarrier::arrive::one.shared::cluster.b64 [%r9];
MMADONE:
    and.b32 %r18, %r17, 1;
WAITL:
    mbarrier.try_wait.parity.acquire.cta.shared::cta.b64 %p6, [%r9], %r18, 10000000;
    @%p6 bra WAITD;
    bra.uni WAITL;
WAITD:
    add.s64 %rd5, %rd5, 128;
    add.s64 %rd6, %rd6, 128;
    add.u32 %r17, %r17, 1;
    setp.lt.u32 %p7, %r17, %r28;
    @%p7 bra KLOOP;

    bar.sync 0;
    tcgen05.fence::after_thread_sync;
    mul.wide.u32 %rd20, %r15, %r5;
    shl.b64 %rd20, %rd20, 1;
    add.s64 %rd20, %rd4, %rd20;
    mul.wide.u32 %rd21, %r2, 256;
    add.s64 %rd20, %rd20, %rd21;

    mov.u32 %r40, %r10;
    tcgen05.ld.sync.aligned.32x32b.x32.b32 {%f0,%f1,%f2,%f3,%f4,%f5,%f6,%f7,%f8,%f9,%f10,%f11,%f12,%f13,%f14,%f15,%f16,%f17,%f18,%f19,%f20,%f21,%f22,%f23,%f24,%f25,%f26,%f27,%f28,%f29,%f30,%f31}, [%r40];
    tcgen05.wait::ld.sync.aligned;
    cvt.rn.f16x2.f32 %r60, %f1, %f0;
    cvt.rn.f16x2.f32 %r61, %f3, %f2;
    cvt.rn.f16x2.f32 %r62, %f5, %f4;
    cvt.rn.f16x2.f32 %r63, %f7, %f6;
    cvt.rn.f16x2.f32 %r64, %f9, %f8;
    cvt.rn.f16x2.f32 %r65, %f11, %f10;
    cvt.rn.f16x2.f32 %r66, %f13, %f12;
    cvt.rn.f16x2.f32 %r67, %f15, %f14;
    cvt.rn.f16x2.f32 %r68, %f17, %f16;
    cvt.rn.f16x2.f32 %r69, %f19, %f18;
    cvt.rn.f16x2.f32 %r70, %f21, %f20;
    cvt.rn.f16x2.f32 %r71, %f23, %f22;
    cvt.rn.f16x2.f32 %r72, %f25, %f24;
    cvt.rn.f16x2.f32 %r73, %f27, %f26;
    cvt.rn.f16x2.f32 %r74, %f29, %f28;
    cvt.rn.f16x2.f32 %r75, %f31, %f30;
    st.global.v4.b32 [%rd20+0],  {%r60,%r61,%r62,%r63};
    st.global.v4.b32 [%rd20+16], {%r64,%r65,%r66,%r67};
    st.global.v4.b32 [%rd20+32], {%r68,%r69,%r70,%r71};
    st.global.v4.b32 [%rd20+48], {%r72,%r73,%r74,%r75};

    add.u32 %r40, %r10, 32;
    tcgen05.ld.sync.aligned.32x32b.x32.b32 {%f0,%f1,%f2,%f3,%f4,%f5,%f6,%f7,%f8,%f9,%f10,%f11,%f12,%f13,%f14,%f15,%f16,%f17,%f18,%f19,%f20,%f21,%f22,%f23,%f24,%f25,%f26,%f27,%f28,%f29,%f30,%f31}, [%r40];
    tcgen05.wait::ld.sync.aligned;
    cvt.rn.f16x2.f32 %r60, %f1, %f0;
    cvt.rn.f16x2.f32 %r61, %f3, %f2;
    cvt.rn.f16x2.f32 %r62, %f5, %f4;
    cvt.rn.f16x2.f32 %r63, %f7, %f6;
    cvt.rn.f16x2.f32 %r64, %f9, %f8;
    cvt.rn.f16x2.f32 %r65, %f11, %f10;
    cvt.rn.f16x2.f32 %r66, %f13, %f12;
    cvt.rn.f16x2.f32 %r67, %f15, %f14;
    cvt.rn.f16x2.f32 %r68, %f17, %f16;
    cvt.rn.f16x2.f32 %r69, %f19, %f18;
    cvt.rn.f16x2.f32 %r70, %f21, %f20;
    cvt.rn.f16x2.f32 %r71, %f23, %f22;
    cvt.rn.f16x2.f32 %r72, %f25, %f24;
    cvt.rn.f16x2.f32 %r73, %f27, %f26;
    cvt.rn.f16x2.f32 %r74, %f29, %f28;
    cvt.rn.f16x2.f32 %r75, %f31, %f30;
    st.global.v4.b32 [%rd20+64], {%r60,%r61,%r62,%r63};
    st.global.v4.b32 [%rd20+80], {%r64,%r65,%r66,%r67};
    st.global.v4.b32 [%rd20+96], {%r68,%r69,%r70,%r71};
    st.global.v4.b32 [%rd20+112], {%r72,%r73,%r74,%r75};

    add.u32 %r40, %r10, 64;
    tcgen05.ld.sync.aligned.32x32b.x32.b32 {%f0,%f1,%f2,%f3,%f4,%f5,%f6,%f7,%f8,%f9,%f10,%f11,%f12,%f13,%f14,%f15,%f16,%f17,%f18,%f19,%f20,%f21,%f22,%f23,%f24,%f25,%f26,%f27,%f28,%f29,%f30,%f31}, [%r40];
    tcgen05.wait::ld.sync.aligned;
    cvt.rn.f16x2.f32 %r60, %f1, %f0;
    cvt.rn.f16x2.f32 %r61, %f3, %f2;
    cvt.rn.f16x2.f32 %r62, %f5, %f4;
    cvt.rn.f16x2.f32 %r63, %f7, %f6;
    cvt.rn.f16x2.f32 %r64, %f9, %f8;
    cvt.rn.f16x2.f32 %r65, %f11, %f10;
    cvt.rn.f16x2.f32 %r66, %f13, %f12;
    cvt.rn.f16x2.f32 %r67, %f15, %f14;
    cvt.rn.f16x2.f32 %r68, %f17, %f16;
    cvt.rn.f16x2.f32 %r69, %f19, %f18;
    cvt.rn.f16x2.f32 %r70, %f21, %f20;
    cvt.rn.f16x2.f32 %r71, %f23, %f22;
    cvt.rn.f16x2.f32 %r72, %f25, %f24;
    cvt.rn.f16x2.f32 %r73, %f27, %f26;
    cvt.rn.f16x2.f32 %r74, %f29, %f28;
    cvt.rn.f16x2.f32 %r75, %f31, %f30;
    st.global.v4.b32 [%rd20+128], {%r60,%r61,%r62,%r63};
    st.global.v4.b32 [%rd20+144], {%r64,%r65,%r66,%r67};
    st.global.v4.b32 [%rd20+160], {%r68,%r69,%r70,%r71};
    st.global.v4.b32 [%rd20+176], {%r72,%r73,%r74,%r75};

    add.u32 %r40, %r10, 96;
    tcgen05.ld.sync.aligned.32x32b.x32.b32 {%f0,%f1,%f2,%f3,%f4,%f5,%f6,%f7,%f8,%f9,%f10,%f11,%f12,%f13,%f14,%f15,%f16,%f17,%f18,%f19,%f20,%f21,%f22,%f23,%f24,%f25,%f26,%f27,%f28,%f29,%f30,%f31}, [%r40];
    tcgen05.wait::ld.sync.aligned;
    cvt.rn.f16x2.f32 %r60, %f1, %f0;
    cvt.rn.f16x2.f32 %r61, %f3, %f2;
    cvt.rn.f16x2.f32 %r62, %f5, %f4;
    cvt.rn.f16x2.f32 %r63, %f7, %f6;
    cvt.rn.f16x2.f32 %r64, %f9, %f8;
    cvt.rn.f16x2.f32 %r65, %f11, %f10;
    cvt.rn.f16x2.f32 %r66, %f13, %f12;
    cvt.rn.f16x2.f32 %r67, %f15, %f14;
    cvt.rn.f16x2.f32 %r68, %f17, %f16;
    cvt.rn.f16x2.f32 %r69, %f19, %f18;
    cvt.rn.f16x2.f32 %r70, %f21, %f20;
    cvt.rn.f16x2.f32 %r71, %f23, %f22;
    cvt.rn.f16x2.f32 %r72, %f25, %f24;
    cvt.rn.f16x2.f32 %r73, %f27, %f26;
    cvt.rn.f16x2.f32 %r74, %f29, %f28;
    cvt.rn.f16x2.f32 %r75, %f31, %f30;
    st.global.v4.b32 [%rd20+192], {%r60,%r61,%r62,%r63};
    st.global.v4.b32 [%rd20+208], {%r64,%r65,%r66,%r67};
    st.global.v4.b32 [%rd20+224], {%r68,%r69,%r70,%r71};
    st.global.v4.b32 [%rd20+240], {%r72,%r73,%r74,%r75};

    bar.sync 0;
    @!%p1 bra SKIPD;
    tcgen05.dealloc.cta_group::1.sync.aligned.b32 %r10, 128;
SKIPD:
    ret;
}
)PTX";

// ---------------------------------------------------------------------------
// CUDA-side helpers
// ---------------------------------------------------------------------------
__device__ __forceinline__ uint32_t smem_u32(const void* p) {
    uint32_t a;
    asm("{ .reg .u64 t; cvta.to.shared.u64 t, %1; cvt.u32.u64 %0, t; }"
        : "=r"(a) : "l"(p));
    return a;
}
__device__ __forceinline__ void cp_async16(uint32_t dst, const void* src) {
    asm volatile("cp.async.cg.shared.global [%0], [%1], 16;"
                 :: "r"(dst), "l"(src) : "memory");
}
__device__ __forceinline__ void cp_commit() {
    asm volatile("cp.async.commit_group;" ::: "memory");
}
template <int N>
__device__ __forceinline__ void cp_wait() {
    asm volatile("cp.async.wait_group %0;" :: "n"(N) : "memory");
}
__device__ __forceinline__ void ldsm4(uint32_t* r, uint32_t addr) {
    asm volatile("ldmatrix.sync.aligned.m8n8.x4.shared.b16 {%0,%1,%2,%3}, [%4];"
                 : "=r"(r[0]), "=r"(r[1]), "=r"(r[2]), "=r"(r[3]) : "r"(addr));
}
__device__ __forceinline__ void ldsm4t(uint32_t* r, uint32_t addr) {
    asm volatile("ldmatrix.sync.aligned.m8n8.x4.trans.shared.b16 {%0,%1,%2,%3}, [%4];"
                 : "=r"(r[0]), "=r"(r[1]), "=r"(r[2]), "=r"(r[3]) : "r"(addr));
}
__device__ __forceinline__ void mma_f16(float (&c)[4],
                                        uint32_t a0, uint32_t a1, uint32_t a2, uint32_t a3,
                                        uint32_t b0, uint32_t b1) {
    asm volatile(
        "mma.sync.aligned.m16n8k16.row.col.f32.f16.f16.f32 "
        "{%0,%1,%2,%3}, {%4,%5,%6,%7}, {%8,%9}, {%0,%1,%2,%3};"
        : "+f"(c[0]), "+f"(c[1]), "+f"(c[2]), "+f"(c[3])
        : "r"(a0), "r"(a1), "r"(a2), "r"(a3), "r"(b0), "r"(b1));
}
__device__ __forceinline__ uint32_t cvt16x2(float hi, float lo) {
    uint32_t d;
    asm("cvt.rn.f16x2.f32 %0, %1, %2;" : "=r"(d) : "f"(hi), "f"(lo));
    return d;
}
__device__ __forceinline__ float ex2f(float x) {
    float r;
    asm("ex2.approx.ftz.f32 %0, %1;" : "=f"(r) : "f"(x));
    return r;
}

// ---------------------------------------------------------------------------
// pre/post-pass kernels
// ---------------------------------------------------------------------------
__global__ __launch_bounds__(256) void cvt_kernel(const float4* __restrict__ s,
                                                  uint2* __restrict__ d, int n4)
{
    int i = blockIdx.x * 256 + threadIdx.x;
    if (i < n4) {
        float4 v = s[i];
        d[i] = make_uint2(cvt16x2(v.y, v.x), cvt16x2(v.w, v.z));
    }
}

__global__ __launch_bounds__(256) void transcvt_kernel(const float* __restrict__ w,
                                                       __half* __restrict__ wt,
                                                       int K, int N)
{
    __shared__ float t[32][33];
    const int n0 = blockIdx.x * 32, k0 = blockIdx.y * 32;
    const int tx = threadIdx.x & 31, ty = threadIdx.x >> 5;
#pragma unroll
    for (int i = 0; i < 4; i++)
        t[ty + 8 * i][tx] = w[(size_t)(k0 + ty + 8 * i) * N + n0 + tx];
    __syncthreads();
#pragma unroll
    for (int i = 0; i < 4; i++)
        wt[(size_t)(n0 + ty + 8 * i) * K + k0 + tx] = __float2half_rn(t[tx][ty + 8 * i]);
}

__global__ __launch_bounds__(256) void bias_out_kernel(const __half2* __restrict__ h,
                                                       const float* __restrict__ bias,
                                                       float2* __restrict__ out, int n2)
{
    int i = blockIdx.x * 256 + threadIdx.x;
    if (i < n2) {
        __half2 v = h[i];
        int col = (i & (DIM / 2 - 1)) * 2;
        float2 o;
        o.x = __low2float(v) + bias[col];
        o.y = __high2float(v) + bias[col + 1];
        out[i] = o;
    }
}

// ---------------------------------------------------------------------------
// Fallback fp16 mma.sync GEMM (used only if JIT fails)
// ---------------------------------------------------------------------------
static constexpr int GEMM_SMEM = 6 * 16384;

template <bool OUT_F32>
__global__ __launch_bounds__(256)
void gemm_h(const __half* __restrict__ A, const __half* __restrict__ Bt,
            const float* __restrict__ bias, void* __restrict__ Cv,
            int M, int N, int K)
{
    extern __shared__ char sm[];
    const uint32_t sb = smem_u32(sm);
    const int tid = threadIdx.x, wid = tid >> 5, lane = tid & 31;
    const int wm = wid >> 2, wn = wid & 3;
    const int bRow = blockIdx.y * 128, bCol = blockIdx.x * 128;
    const int crow = tid >> 1, cc0 = (tid & 1) * 4;
    const __half* Arow = A + (size_t)(bRow + crow) * K;
    const __half* Brow = Bt + (size_t)(bCol + crow) * K;
    const int r8 = lane & 7;
    const int hA = (lane >> 3) & 1, gA = (lane >> 4) & 1;
    const int gB = (lane >> 3) & 1, hB = (lane >> 4) & 1;

    float acc[4][4][4];
#pragma unroll
    for (int i = 0; i < 4; i++)
#pragma unroll
        for (int j = 0; j < 4; j++)
#pragma unroll
            for (int v = 0; v < 4; v++) acc[i][j][v] = 0.f;

    auto stage = [&](int kc, int s) {
        const uint32_t ab = sb + (uint32_t)s * 16384u;
        const uint32_t bb = sb + 49152u + (uint32_t)s * 16384u;
        const uint32_t soff = (uint32_t)crow * 128u;
#pragma unroll
        for (int i = 0; i < 4; i++) {
            int c = cc0 + i;
            uint32_t sw = soff + 16u * (uint32_t)(c ^ (crow & 7));
            cp_async16(ab + sw, Arow + kc * 64 + c * 8);
            cp_async16(bb + sw, Brow + kc * 64 + c * 8);
        }
        cp_commit();
    };

    const int NC = K / 64;
    stage(0, 0); stage(1, 1);

#pragma unroll 1
    for (int kc = 0; kc < NC; kc++) {
        const int s = kc % 3;
        if (kc < NC - 1) cp_wait<1>(); else cp_wait<0>();
        __syncthreads();
        const uint32_t aB = sb + (uint32_t)s * 16384u;
        const uint32_t bB = sb + 49152u + (uint32_t)s * 16384u;
#pragma unroll
        for (int ks = 0; ks < 4; ks++) {
            uint32_t breg[2][4];
#pragma unroll
            for (int np = 0; np < 2; np++) {
                int nrow = wn * 32 + np * 16 + hB * 8 + r8;
                int ch = 2 * ks + gB;
                ldsm4(breg[np], bB + (uint32_t)nrow * 128u + 16u * (uint32_t)(ch ^ (nrow & 7)));
            }
#pragma unroll
            for (int mi = 0; mi < 4; mi++) {
                uint32_t areg[4];
                int arow = wm * 64 + mi * 16 + hA * 8 + r8;
                int ch = 2 * ks + gA;
                ldsm4(areg, aB + (uint32_t)arow * 128u + 16u * (uint32_t)(ch ^ (arow & 7)));
#pragma unroll
                for (int ni = 0; ni < 4; ni++) {
                    const uint32_t* br = breg[ni >> 1];
                    int off = (ni & 1) * 2;
                    mma_f16(acc[mi][ni], areg[0], areg[1], areg[2], areg[3], br[off], br[off + 1]);
                }
            }
        }
        if (kc + 2 < NC) stage(kc + 2, (kc + 2) % 3);
    }

    const int erow = lane >> 2, ecol = (lane & 3) * 2;
#pragma unroll
    for (int mi = 0; mi < 4; mi++)
#pragma unroll
        for (int ni = 0; ni < 4; ni++) {
            int col = bCol + wn * 32 + ni * 8 + ecol;
            int r0 = bRow + wm * 64 + mi * 16 + erow;
            if (OUT_F32) {
                float* C = (float*)Cv;
                float bx = bias[col], by = bias[col + 1];
                float2 v0 = { acc[mi][ni][0] + bx, acc[mi][ni][1] + by };
                float2 v1 = { acc[mi][ni][2] + bx, acc[mi][ni][3] + by };
                *(float2*)(C + (size_t)r0 * N + col) = v0;
                *(float2*)(C + (size_t)(r0 + 8) * N + col) = v1;
            } else {
                __half* C = (__half*)Cv;
                *(uint32_t*)(C + (size_t)r0 * N + col) = cvt16x2(acc[mi][ni][1], acc[mi][ni][0]);
                *(uint32_t*)(C + (size_t)(r0 + 8) * N + col) = cvt16x2(acc[mi][ni][3], acc[mi][ni][2]);
            }
        }
}

// ---------------------------------------------------------------------------
// Flash attention (unchanged)
// ---------------------------------------------------------------------------
__global__ __launch_bounds__(256, 2) void attn_fa(int b)
{
    const int h = blockIdx.y, tid = threadIdx.x;
    const int warp = tid >> 5, lane = tid & 31;

    __shared__ __align__(16) char sm[49152];
    const uint32_t base = smem_u32(sm);
    const __half* qkvB = g_qkv_h + (size_t)b * SEQ * (3 * DIM);

    const int rloc = warp * 16 + (lane >> 2);
    const int grow_lo = blockIdx.x * 128 + rloc;
    const __half* qp_lo = qkvB + (size_t)grow_lo * (3 * DIM) + h * HD;
    const __half* qp_hi = qp_lo + (size_t)8 * (3 * DIM);

    const __half2 csc2 = __float2half2_rn(CSC);
    uint32_t qf[4][4];
#pragma unroll
    for (int j = 0; j < 4; j++) {
        int k0 = j * 16 + 2 * (lane & 3);
        __half2 v;
        v = __hmul2(*(const __half2*)(qp_lo + k0),     csc2); qf[j][0] = *(uint32_t*)&v;
        v = __hmul2(*(const __half2*)(qp_hi + k0),     csc2); qf[j][1] = *(uint32_t*)&v;
        v = __hmul2(*(const __half2*)(qp_lo + k0 + 8), csc2); qf[j][2] = *(uint32_t*)&v;
        v = __hmul2(*(const __half2*)(qp_hi + k0 + 8), csc2); qf[j][3] = *(uint32_t*)&v;
    }

    float O[8][4];
#pragma unroll
    for (int i = 0; i < 8; i++)
#pragma unroll
        for (int c = 0; c < 4; c++) O[i][c] = 0.f;
    float l_lo = 0.f, l_hi = 0.f;
    float m_lo = -1e30f, m_hi = -1e30f;

    auto stage = [&](int j0, int s) {
#pragma unroll
        for (int i = 0; i < 2; i++) {
            int id = i * 256 + tid;
            int row = id >> 3, c = id & 7;
            const __half* kr = qkvB + (size_t)(j0 + row) * (3 * DIM) + DIM + h * HD + c * 8;
            uint32_t dst = base + (uint32_t)s * 8192u +
                           (uint32_t)row * 128u + 16u * (uint32_t)(c ^ (row & 7));
            cp_async16(dst, kr);
            cp_async16(dst + 24576u, kr + DIM);
        }
        cp_commit();
    };

    const int NT = SEQ / 64;
    stage(0, 0); stage(64, 1);

#pragma unroll 1
    for (int t = 0; t < NT; t++) {
        const int s = t % 3;
        if (t < NT - 1) cp_wait<1>(); else cp_wait<0>();
        __syncthreads();
        if (t + 2 < NT) stage((t + 2) * 64, (t + 2) % 3);

        const uint32_t kB = base + (uint32_t)s * 8192u;
        const uint32_t vB = kB + 24576u;

        float S[8][4];
#pragma unroll
        for (int nt = 0; nt < 8; nt++)
#pragma unroll
            for (int c = 0; c < 4; c++) S[nt][c] = 0.f;

#pragma unroll
        for (int blk = 0; blk < 2; blk++) {
            uint32_t bk[4][8];
#pragma unroll
            for (int i = 0; i < 4; i++) {
                int nt = blk * 4 + i;
#pragma unroll
                for (int ks2 = 0; ks2 < 2; ks2++) {
                    int mrow = 8 * nt + (lane & 7);
                    int chunk = ks2 * 4 + (lane >> 3);
                    ldsm4(&bk[i][ks2 * 4],
                          kB + (uint32_t)mrow * 128u + 16u * (uint32_t)(chunk ^ (mrow & 7)));
                }
            }
#pragma unroll
            for (int ks = 0; ks < 4; ks++)
#pragma unroll
                for (int i = 0; i < 4; i++)
                    mma_f16(S[blk * 4 + i], qf[ks][0], qf[ks][1], qf[ks][2], qf[ks][3],
                            bk[i][2 * ks], bk[i][2 * ks + 1]);
        }

        float tmax_lo = -1e30f, tmax_hi = -1e30f;
#pragma unroll
        for (int nt = 0; nt < 8; nt++) {
            tmax_lo = fmaxf(tmax_lo, fmaxf(S[nt][0], S[nt][1]));
            tmax_hi = fmaxf(tmax_hi, fmaxf(S[nt][2], S[nt][3]));
        }
        tmax_lo = fmaxf(tmax_lo, __shfl_xor_sync(0xffffffffu, tmax_lo, 1));
        tmax_lo = fmaxf(tmax_lo, __shfl_xor_sync(0xffffffffu, tmax_lo, 2));
        tmax_hi = fmaxf(tmax_hi, __shfl_xor_sync(0xffffffffu, tmax_hi, 1));
        tmax_hi = fmaxf(tmax_hi, __shfl_xor_sync(0xffffffffu, tmax_hi, 2));

        const float mn_lo = fmaxf(m_lo, tmax_lo);
        const float mn_hi = fmaxf(m_hi, tmax_hi);
        const float al = ex2f(m_lo - mn_lo);
        const float ah = ex2f(m_hi - mn_hi);
        m_lo = mn_lo; m_hi = mn_hi;

#pragma unroll
        for (int nt = 0; nt < 8; nt++) {
            O[nt][0] *= al; O[nt][1] *= al; O[nt][2] *= ah; O[nt][3] *= ah;
        }
        l_lo *= al; l_hi *= ah;

        uint32_t P[8][2];
#pragma unroll
        for (int nt = 0; nt < 8; nt++) {
            float p0 = ex2f(S[nt][0] - mn_lo);
            float p1 = ex2f(S[nt][1] - mn_lo);
            float p2 = ex2f(S[nt][2] - mn_hi);
            float p3 = ex2f(S[nt][3] - mn_hi);
            P[nt][0] = cvt16x2(p1, p0);
            P[nt][1] = cvt16x2(p3, p2);
            l_lo += p0 + p1;
            l_hi += p2 + p3;
        }

#pragma unroll
        for (int blk = 0; blk < 2; blk++) {
            uint32_t bv[4][8];
#pragma unroll
            for (int i = 0; i < 4; i++) {
                int nt = blk * 4 + i;
#pragma unroll
                for (int kp = 0; kp < 2; kp++) {
                    int mrow = 32 * kp + 8 * (lane >> 3) + (lane & 7);
                    ldsm4t(&bv[i][kp * 4],
                           vB + (uint32_t)mrow * 128u + 16u * (uint32_t)(nt ^ (mrow & 7)));
                }
            }
#pragma unroll
            for (int ks = 0; ks < 4; ks++)
#pragma unroll
                for (int i = 0; i < 4; i++)
                    mma_f16(O[blk * 4 + i],
                            P[2 * ks][0], P[2 * ks][1], P[2 * ks + 1][0], P[2 * ks + 1][1],
                            bv[i][2 * ks], bv[i][2 * ks + 1]);
        }
    }

    l_lo += __shfl_xor_sync(0xffffffffu, l_lo, 1);
    l_lo += __shfl_xor_sync(0xffffffffu, l_lo, 2);
    l_hi += __shfl_xor_sync(0xffffffffu, l_hi, 1);
    l_hi += __shfl_xor_sync(0xffffffffu, l_hi, 2);
    const float inv_lo = 1.f / l_lo;
    const float inv_hi = 1.f / l_hi;
    __half* orow_lo = g_attn_h + ((size_t)(b * SEQ) + grow_lo) * DIM + h * HD;
    __half* orow_hi = orow_lo + (size_t)8 * DIM;
#pragma unroll
    for (int nt = 0; nt < 8; nt++) {
        int col = nt * 8 + 2 * (lane & 3);
        *(uint32_t*)(orow_lo + col) = cvt16x2(O[nt][1] * inv_lo, O[nt][0] * inv_lo);
        *(uint32_t*)(orow_hi + col) = cvt16x2(O[nt][3] * inv_hi, O[nt][2] * inv_hi);
    }
}

// ---------------------------------------------------------------------------
// launcher — all launches on EXPLICIT streams (driver API must never see the
// legacy NULL stream during capture). Handles created on the first call.
// ---------------------------------------------------------------------------
typedef CUresult (*PFN_cuModuleLoadDataEx)(CUmodule*, const void*, unsigned int,
                                           CUjit_option*, void**);
typedef CUresult (*PFN_cuModuleGetFunction)(CUfunction*, CUmodule, const char*);
typedef CUresult (*PFN_cuLaunchKernel)(CUfunction, unsigned, unsigned, unsigned,
                                       unsigned, unsigned, unsigned,
                                       unsigned, CUstream, void**, void**);

static PFN_cuLaunchKernel s_culaunch = nullptr;
static CUfunction s_gemmt5 = nullptr;
static bool s_t5 = false;

static inline void t5_gemm(const __half* A, const __half* B, __half* C,
                           int N, int K, int M, cudaStream_t st)
{
    void* args[5] = { (void*)&A, (void*)&B, (void*)&C, (void*)&N, (void*)&K };
    s_culaunch(s_gemmt5, (unsigned)(N / 128), (unsigned)(M / 128), 1,
               128, 1, 1, 0, (CUstream)st, args, nullptr);
}

extern "C" void kernel_launch(void* const* d_in, const int* in_sizes, int n_in,
                              void* d_out, int out_size)
{
    const float* x     = (const float*)d_in[0];
    const float* w_qkv = (const float*)d_in[1];
    const float* w_out = (const float*)d_in[2];
    const float* b_out = (const float*)d_in[3];
    float*       out   = (float*)d_out;

    __half *xh, *wqkvh, *wouth, *qkvh, *attnh;
    cudaGetSymbolAddress((void**)&xh,    g_x_h);
    cudaGetSymbolAddress((void**)&wqkvh, g_wqkv_h);
    cudaGetSymbolAddress((void**)&wouth, g_wout_h);
    cudaGetSymbolAddress((void**)&qkvh,  g_qkv_h);
    cudaGetSymbolAddress((void**)&attnh, g_attn_h);

    static bool inited = false;
    static cudaStream_t s0, s1, s2;
    static cudaEvent_t eFork, eDone;
    static cudaEvent_t eX[BATCH], eQ[BATCH], eA[BATCH];
    if (!inited) {
        cudaStreamCreateWithFlags(&s0, cudaStreamNonBlocking);
        cudaStreamCreateWithFlags(&s1, cudaStreamNonBlocking);
        cudaStreamCreateWithFlags(&s2, cudaStreamNonBlocking);
        cudaEventCreateWithFlags(&eFork, cudaEventDisableTiming);
        cudaEventCreateWithFlags(&eDone, cudaEventDisableTiming);
        for (int b = 0; b < BATCH; b++) {
            cudaEventCreateWithFlags(&eX[b], cudaEventDisableTiming);
            cudaEventCreateWithFlags(&eQ[b], cudaEventDisableTiming);
            cudaEventCreateWithFlags(&eA[b], cudaEventDisableTiming);
        }
        cudaFuncSetAttribute(gemm_h<false>,
                             cudaFuncAttributeMaxDynamicSharedMemorySize, GEMM_SMEM);
        cudaFuncSetAttribute(gemm_h<true>,
                             cudaFuncAttributeMaxDynamicSharedMemorySize, GEMM_SMEM);

        void* hcu = dlopen("libcuda.so.1", RTLD_NOW | RTLD_GLOBAL);
        if (hcu) {
            auto pLoad = (PFN_cuModuleLoadDataEx)dlsym(hcu, "cuModuleLoadDataEx");
            auto pGetF = (PFN_cuModuleGetFunction)dlsym(hcu, "cuModuleGetFunction");
            s_culaunch = (PFN_cuLaunchKernel)dlsym(hcu, "cuLaunchKernel");
            if (pLoad && pGetF && s_culaunch) {
                static char elog[8192];
                CUjit_option opts[2] = { CU_JIT_ERROR_LOG_BUFFER,
                                         CU_JIT_ERROR_LOG_BUFFER_SIZE_BYTES };
                void* vals[2] = { (void*)elog, (void*)(size_t)sizeof(elog) };
                CUmodule mod;
                CUresult rc = pLoad(&mod, PTX_SRC, 2, opts, vals);
                if (rc == CUDA_SUCCESS &&
                    pGetF(&s_gemmt5, mod, "gemm_t5") == CUDA_SUCCESS) {
                    s_t5 = true;
                } else {
                    printf("T5 JIT failed rc=%d\n%s\n", (int)rc, elog);
                }
            }
        }
        inited = true;
    }

    const int BR = SEQ;
    const int n4b = BR * DIM / 4;

    // fork from the (per-thread) default stream into explicit streams
    cudaEventRecord(eFork, 0);
    cudaStreamWaitEvent(s0, eFork, 0);
    cudaStreamWaitEvent(s1, eFork, 0);
    cudaStreamWaitEvent(s2, eFork, 0);

    // s2: input converts + wout transpose
    for (int b = 0; b < BATCH; b++) {
        cvt_kernel<<<n4b / 256, 256, 0, s2>>>(
            (const float4*)(x + (size_t)b * BR * DIM),
            (uint2*)(xh + (size_t)b * BR * DIM), n4b);
        cudaEventRecord(eX[b], s2);
    }
    transcvt_kernel<<<dim3(DIM / 32, DIM / 32), 256, 0, s2>>>(w_out, wouth, DIM, DIM);

    // s0: qkv weight transpose + per-batch QKV GEMMs
    transcvt_kernel<<<dim3(3 * DIM / 32, DIM / 32), 256, 0, s0>>>(w_qkv, wqkvh, DIM, 3 * DIM);
    for (int b = 0; b < BATCH; b++) {
        cudaStreamWaitEvent(s0, eX[b], 0);
        if (s_t5)
            t5_gemm(xh + (size_t)b * BR * DIM, wqkvh,
                    qkvh + (size_t)b * BR * 3 * DIM, 3 * DIM, DIM, BR, s0);
        else
            gemm_h<false><<<dim3(3 * DIM / 128, BR / 128), 256, GEMM_SMEM, s0>>>(
                xh + (size_t)b * BR * DIM, wqkvh, nullptr,
                qkvh + (size_t)b * BR * 3 * DIM, BR, 3 * DIM, DIM);
        cudaEventRecord(eQ[b], s0);

        cudaStreamWaitEvent(s1, eQ[b], 0);
        attn_fa<<<dim3(SEQ / 128, NH, 1), 256, 0, s1>>>(b);
        cudaEventRecord(eA[b], s1);

        cudaStreamWaitEvent(s2, eA[b], 0);
        if (s_t5) {
            t5_gemm(attnh + (size_t)b * BR * DIM, wouth,
                    xh + (size_t)b * BR * DIM, DIM, DIM, BR, s2);
            int n2 = BR * DIM / 2;
            bias_out_kernel<<<(n2 + 255) / 256, 256, 0, s2>>>(
                (const __half2*)(xh + (size_t)b * BR * DIM), b_out,
                (float2*)(out + (size_t)b * BR * DIM), n2);
        } else {
            gemm_h<true><<<dim3(DIM / 128, BR / 128), 256, GEMM_SMEM, s2>>>(
                attnh + (size_t)b * BR * DIM, wouth, b_out,
                out + (size_t)b * BR * DIM, BR, DIM, DIM);
        }
    }

    cudaEventRecord(eDone, s2);
    cudaStreamWaitEvent(0, eDone, 0);
}

// round 15
// speedup vs baseline: 1.2763x; 1.2763x over previous
#include <cuda_runtime.h>
#include <cuda_fp16.h>
#include <cuda.h>
#include <dlfcn.h>
#include <cstdint>
#include <cstdio>
#include <math.h>

#define DIM   1024
#define NH    16
#define HD    64
#define BATCH 4
#define SEQ   2048
#define CSC   0.18033688011112042f   /* 64^-0.5 * log2(e) */

#define MROWS (BATCH * SEQ)          /* 8192 */

__device__ __half g_x_h   [(size_t)MROWS * DIM];      // reused as f16 out-proj result
__device__ __half g_wqkv_h[(size_t)3 * DIM * DIM];    // [N][K]
__device__ __half g_wout_h[(size_t)DIM * DIM];        // [N][K]
__device__ __half g_qkv_h [(size_t)MROWS * 3 * DIM];
__device__ __half g_attn_h[(size_t)MROWS * DIM];

// ===========================================================================
// tcgen05 GEMM PTX (JIT, .target sm_103a).  Double-buffered pipeline:
// stage chunk k+1 while mma of chunk k runs; per-buffer mbarriers gate reuse.
// Dynamic smem: header @dsm (tmem ptr, 2 mbars), buffers @1024-aligned base:
// A0 @0, B0 @16K, A1 @32K, B1 @48K (relative to base).
// ===========================================================================
static const char* PTX_SRC = R"PTX(
.version 8.8
.target sm_103a
.address_size 64

.visible .entry gemm_t5(
    .param .u64 pA,
    .param .u64 pB,
    .param .u64 pC,
    .param .u32 pN,
    .param .u32 pK
)
{
    .reg .pred %p<16>;
    .reg .b32 %r<90>;
    .reg .f32 %f<40>;
    .reg .b64 %rd<40>;
    .extern .shared .align 16 .b8 dsm[];

    mov.u32 %r1, %tid.x;
    mov.u32 %r2, %ctaid.x;
    mov.u32 %r3, %ctaid.y;
    mov.u32 %r4, dsm;

    ld.param.u64 %rd1, [pA];
    ld.param.u64 %rd2, [pB];
    ld.param.u64 %rd4, [pC];
    ld.param.u32 %r5, [pN];
    ld.param.u32 %r6, [pK];
    cvta.to.global.u64 %rd1, %rd1;
    cvta.to.global.u64 %rd2, %rd2;
    cvta.to.global.u64 %rd4, %rd4;

    // 1024-aligned buffer base (header stays at dsm)
    add.u32 %r7, %r4, 2047;
    and.b32 %r7, %r7, 0xfffffc00;

    shr.u32 %r8, %r1, 5;
    setp.eq.u32 %p1, %r8, 0;
    add.u32 %r9, %r4, 8;
    @!%p1 bra SKIPA;
    tcgen05.alloc.cta_group::1.sync.aligned.shared::cta.b32 [%r4], 128;
    tcgen05.relinquish_alloc_permit.cta_group::1.sync.aligned;
SKIPA:
    setp.eq.u32 %p2, %r1, 0;
    @%p2 mbarrier.init.shared.b64 [%r9], 1;
    @%p2 mbarrier.init.shared.b64 [%r9+8], 1;
    bar.sync 0;
    ld.shared.b32 %r10, [%r4];

    // swizzle offsets relative to a buffer base: tid*128 + 16*(c ^ (tid&7))
    and.b32 %r11, %r1, 7;
    shl.b32 %r13, %r1, 7;
    shl.b32 %r14, %r11, 4;
    add.u32 %r20, %r13, %r14;
    xor.b32 %r14, %r11, 1; shl.b32 %r14, %r14, 4; add.u32 %r21, %r13, %r14;
    xor.b32 %r14, %r11, 2; shl.b32 %r14, %r14, 4; add.u32 %r22, %r13, %r14;
    xor.b32 %r14, %r11, 3; shl.b32 %r14, %r14, 4; add.u32 %r23, %r13, %r14;
    xor.b32 %r14, %r11, 4; shl.b32 %r14, %r14, 4; add.u32 %r24, %r13, %r14;
    xor.b32 %r14, %r11, 5; shl.b32 %r14, %r14, 4; add.u32 %r25, %r13, %r14;
    xor.b32 %r14, %r11, 6; shl.b32 %r14, %r14, 4; add.u32 %r26, %r13, %r14;
    xor.b32 %r14, %r11, 7; shl.b32 %r14, %r14, 4; add.u32 %r27, %r13, %r14;

    mad.lo.u32 %r15, %r3, 128, %r1;
    mul.wide.u32 %rd5, %r15, %r6;
    shl.b64 %rd5, %rd5, 1;
    add.s64 %rd5, %rd1, %rd5;
    mad.lo.u32 %r16, %r2, 128, %r1;
    mul.wide.u32 %rd6, %r16, %r6;
    shl.b64 %rd6, %rd6, 1;
    add.s64 %rd6, %rd2, %rd6;

    mov.u64 %rd11, 0x4000004000010000;
    mov.u32 %r33, 0x08200010;
    mov.u32 %r34, 0;
    shr.u32 %r28, %r6, 6;
    mov.u32 %r17, 0;
    mov.u32 %r36, 0;
    mov.u32 %r37, 0;

    // prologue: stage chunk 0 into buf0
    mov.u32 %r51, %r7;
    add.u32 %r60, %r51, %r20;
    add.u32 %r61, %r51, %r21;
    add.u32 %r62, %r51, %r22;
    add.u32 %r63, %r51, %r23;
    add.u32 %r64, %r51, %r24;
    add.u32 %r65, %r51, %r25;
    add.u32 %r66, %r51, %r26;
    add.u32 %r67, %r51, %r27;
    cp.async.cg.shared.global [%r60], [%rd5], 16;
    cp.async.cg.shared.global [%r61], [%rd5+16], 16;
    cp.async.cg.shared.global [%r62], [%rd5+32], 16;
    cp.async.cg.shared.global [%r63], [%rd5+48], 16;
    cp.async.cg.shared.global [%r64], [%rd5+64], 16;
    cp.async.cg.shared.global [%r65], [%rd5+80], 16;
    cp.async.cg.shared.global [%r66], [%rd5+96], 16;
    cp.async.cg.shared.global [%r67], [%rd5+112], 16;
    cp.async.cg.shared.global [%r60+16384], [%rd6], 16;
    cp.async.cg.shared.global [%r61+16384], [%rd6+16], 16;
    cp.async.cg.shared.global [%r62+16384], [%rd6+32], 16;
    cp.async.cg.shared.global [%r63+16384], [%rd6+48], 16;
    cp.async.cg.shared.global [%r64+16384], [%rd6+64], 16;
    cp.async.cg.shared.global [%r65+16384], [%rd6+80], 16;
    cp.async.cg.shared.global [%r66+16384], [%rd6+96], 16;
    cp.async.cg.shared.global [%r67+16384], [%rd6+112], 16;
    cp.async.commit_group;
    add.s64 %rd5, %rd5, 128;
    add.s64 %rd6, %rd6, 128;

KLOOP:
    and.b32 %r50, %r17, 1;
    shl.b32 %r53, %r50, 15;
    add.u32 %r51, %r7, %r53;
    cp.async.wait_group 0;
    bar.sync 0;
    @!%p2 bra NOMMA;
    fence.proxy.async.shared::cta;
    shr.u32 %r55, %r51, 4;
    and.b32 %r55, %r55, 16383;
    cvt.u64.u32 %rd10, %r55;
    or.b64 %rd10, %rd10, %rd11;
    add.u32 %r56, %r51, 16384;
    shr.u32 %r55, %r56, 4;
    and.b32 %r55, %r55, 16383;
    cvt.u64.u32 %rd12, %r55;
    or.b64 %rd12, %rd12, %rd11;
    setp.ne.u32 %p3, %r17, 0;
    tcgen05.mma.cta_group::1.kind::f16 [%r10], %rd10, %rd12, %r33, {%r34, %r34, %r34, %r34}, %p3;
    setp.eq.u32 %p5, %r34, 0;
    add.s64 %rd13, %rd10, 2;
    add.s64 %rd14, %rd12, 2;
    tcgen05.mma.cta_group::1.kind::f16 [%r10], %rd13, %rd14, %r33, {%r34, %r34, %r34, %r34}, %p5;
    add.s64 %rd13, %rd10, 4;
    add.s64 %rd14, %rd12, 4;
    tcgen05.mma.cta_group::1.kind::f16 [%r10], %rd13, %rd14, %r33, {%r34, %r34, %r34, %r34}, %p5;
    add.s64 %rd13, %rd10, 6;
    add.s64 %rd14, %rd12, 6;
    tcgen05.mma.cta_group::1.kind::f16 [%r10], %rd13, %rd14, %r33, {%r34, %r34, %r34, %r34}, %p5;
    shl.b32 %r57, %r50, 3;
    add.u32 %r58, %r9, %r57;
    tcgen05.commit.cta_group::1.mbarrier::arrive::one.shared::cluster.b64 [%r58];
NOMMA:
    add.u32 %r59, %r17, 1;
    setp.ge.u32 %p8, %r59, %r28;
    @%p8 bra NOSTAGE;
    xor.b32 %r52, %r50, 1;
    setp.eq.u32 %p9, %r17, 0;
    @%p9 bra NOWAIT;
    shl.b32 %r57, %r52, 3;
    add.u32 %r58, %r9, %r57;
    setp.eq.u32 %p10, %r52, 0;
    selp.b32 %r54, %r36, %r37, %p10;
WL2:
    mbarrier.try_wait.parity.acquire.cta.shared::cta.b64 %p6, [%r58], %r54, 10000000;
    @%p6 bra WD2;
    bra.uni WL2;
WD2:
    xor.b32 %r54, %r54, 1;
    @%p10 mov.u32 %r36, %r54;
    @!%p10 mov.u32 %r37, %r54;
NOWAIT:
    shl.b32 %r53, %r52, 15;
    add.u32 %r51, %r7, %r53;
    add.u32 %r60, %r51, %r20;
    add.u32 %r61, %r51, %r21;
    add.u32 %r62, %r51, %r22;
    add.u32 %r63, %r51, %r23;
    add.u32 %r64, %r51, %r24;
    add.u32 %r65, %r51, %r25;
    add.u32 %r66, %r51, %r26;
    add.u32 %r67, %r51, %r27;
    cp.async.cg.shared.global [%r60], [%rd5], 16;
    cp.async.cg.shared.global [%r61], [%rd5+16], 16;
    cp.async.cg.shared.global [%r62], [%rd5+32], 16;
    cp.async.cg.shared.global [%r63], [%rd5+48], 16;
    cp.async.cg.shared.global [%r64], [%rd5+64], 16;
    cp.async.cg.shared.global [%r65], [%rd5+80], 16;
    cp.async.cg.shared.global [%r66], [%rd5+96], 16;
    cp.async.cg.shared.global [%r67], [%rd5+112], 16;
    cp.async.cg.shared.global [%r60+16384], [%rd6], 16;
    cp.async.cg.shared.global [%r61+16384], [%rd6+16], 16;
    cp.async.cg.shared.global [%r62+16384], [%rd6+32], 16;
    cp.async.cg.shared.global [%r63+16384], [%rd6+48], 16;
    cp.async.cg.shared.global [%r64+16384], [%rd6+64], 16;
    cp.async.cg.shared.global [%r65+16384], [%rd6+80], 16;
    cp.async.cg.shared.global [%r66+16384], [%rd6+96], 16;
    cp.async.cg.shared.global [%r67+16384], [%rd6+112], 16;
    cp.async.commit_group;
    add.s64 %rd5, %rd5, 128;
    add.s64 %rd6, %rd6, 128;
NOSTAGE:
    add.u32 %r17, %r17, 1;
    setp.lt.u32 %p7, %r17, %r28;
    @%p7 bra KLOOP;

    // drain both mbars (one outstanding commit each)
WF0:
    mbarrier.try_wait.parity.acquire.cta.shared::cta.b64 %p6, [%r9], %r36, 10000000;
    @%p6 bra WF0D;
    bra.uni WF0;
WF0D:
WF1:
    mbarrier.try_wait.parity.acquire.cta.shared::cta.b64 %p6, [%r9+8], %r37, 10000000;
    @%p6 bra WF1D;
    bra.uni WF1;
WF1D:
    bar.sync 0;
    tcgen05.fence::after_thread_sync;
    mul.wide.u32 %rd20, %r15, %r5;
    shl.b64 %rd20, %rd20, 1;
    add.s64 %rd20, %rd4, %rd20;
    mul.wide.u32 %rd21, %r2, 256;
    add.s64 %rd20, %rd20, %rd21;

    mov.u32 %r40, %r10;
    tcgen05.ld.sync.aligned.32x32b.x32.b32 {%f0,%f1,%f2,%f3,%f4,%f5,%f6,%f7,%f8,%f9,%f10,%f11,%f12,%f13,%f14,%f15,%f16,%f17,%f18,%f19,%f20,%f21,%f22,%f23,%f24,%f25,%f26,%f27,%f28,%f29,%f30,%f31}, [%r40];
    tcgen05.wait::ld.sync.aligned;
    cvt.rn.f16x2.f32 %r60, %f1, %f0;
    cvt.rn.f16x2.f32 %r61, %f3, %f2;
    cvt.rn.f16x2.f32 %r62, %f5, %f4;
    cvt.rn.f16x2.f32 %r63, %f7, %f6;
    cvt.rn.f16x2.f32 %r64, %f9, %f8;
    cvt.rn.f16x2.f32 %r65, %f11, %f10;
    cvt.rn.f16x2.f32 %r66, %f13, %f12;
    cvt.rn.f16x2.f32 %r67, %f15, %f14;
    cvt.rn.f16x2.f32 %r68, %f17, %f16;
    cvt.rn.f16x2.f32 %r69, %f19, %f18;
    cvt.rn.f16x2.f32 %r70, %f21, %f20;
    cvt.rn.f16x2.f32 %r71, %f23, %f22;
    cvt.rn.f16x2.f32 %r72, %f25, %f24;
    cvt.rn.f16x2.f32 %r73, %f27, %f26;
    cvt.rn.f16x2.f32 %r74, %f29, %f28;
    cvt.rn.f16x2.f32 %r75, %f31, %f30;
    st.global.v4.b32 [%rd20+0],  {%r60,%r61,%r62,%r63};
    st.global.v4.b32 [%rd20+16], {%r64,%r65,%r66,%r67};
    st.global.v4.b32 [%rd20+32], {%r68,%r69,%r70,%r71};
    st.global.v4.b32 [%rd20+48], {%r72,%r73,%r74,%r75};

    add.u32 %r40, %r10, 32;
    tcgen05.ld.sync.aligned.32x32b.x32.b32 {%f0,%f1,%f2,%f3,%f4,%f5,%f6,%f7,%f8,%f9,%f10,%f11,%f12,%f13,%f14,%f15,%f16,%f17,%f18,%f19,%f20,%f21,%f22,%f23,%f24,%f25,%f26,%f27,%f28,%f29,%f30,%f31}, [%r40];
    tcgen05.wait::ld.sync.aligned;
    cvt.rn.f16x2.f32 %r60, %f1, %f0;
    cvt.rn.f16x2.f32 %r61, %f3, %f2;
    cvt.rn.f16x2.f32 %r62, %f5, %f4;
    cvt.rn.f16x2.f32 %r63, %f7, %f6;
    cvt.rn.f16x2.f32 %r64, %f9, %f8;
    cvt.rn.f16x2.f32 %r65, %f11, %f10;
    cvt.rn.f16x2.f32 %r66, %f13, %f12;
    cvt.rn.f16x2.f32 %r67, %f15, %f14;
    cvt.rn.f16x2.f32 %r68, %f17, %f16;
    cvt.rn.f16x2.f32 %r69, %f19, %f18;
    cvt.rn.f16x2.f32 %r70, %f21, %f20;
    cvt.rn.f16x2.f32 %r71, %f23, %f22;
    cvt.rn.f16x2.f32 %r72, %f25, %f24;
    cvt.rn.f16x2.f32 %r73, %f27, %f26;
    cvt.rn.f16x2.f32 %r74, %f29, %f28;
    cvt.rn.f16x2.f32 %r75, %f31, %f30;
    st.global.v4.b32 [%rd20+64], {%r60,%r61,%r62,%r63};
    st.global.v4.b32 [%rd20+80], {%r64,%r65,%r66,%r67};
    st.global.v4.b32 [%rd20+96], {%r68,%r69,%r70,%r71};
    st.global.v4.b32 [%rd20+112], {%r72,%r73,%r74,%r75};

    add.u32 %r40, %r10, 64;
    tcgen05.ld.sync.aligned.32x32b.x32.b32 {%f0,%f1,%f2,%f3,%f4,%f5,%f6,%f7,%f8,%f9,%f10,%f11,%f12,%f13,%f14,%f15,%f16,%f17,%f18,%f19,%f20,%f21,%f22,%f23,%f24,%f25,%f26,%f27,%f28,%f29,%f30,%f31}, [%r40];
    tcgen05.wait::ld.sync.aligned;
    cvt.rn.f16x2.f32 %r60, %f1, %f0;
    cvt.rn.f16x2.f32 %r61, %f3, %f2;
    cvt.rn.f16x2.f32 %r62, %f5, %f4;
    cvt.rn.f16x2.f32 %r63, %f7, %f6;
    cvt.rn.f16x2.f32 %r64, %f9, %f8;
    cvt.rn.f16x2.f32 %r65, %f11, %f10;
    cvt.rn.f16x2.f32 %r66, %f13, %f12;
    cvt.rn.f16x2.f32 %r67, %f15, %f14;
    cvt.rn.f16x2.f32 %r68, %f17, %f16;
    cvt.rn.f16x2.f32 %r69, %f19, %f18;
    cvt.rn.f16x2.f32 %r70, %f21, %f20;
    cvt.rn.f16x2.f32 %r71, %f23, %f22;
    cvt.rn.f16x2.f32 %r72, %f25, %f24;
    cvt.rn.f16x2.f32 %r73, %f27, %f26;
    cvt.rn.f16x2.f32 %r74, %f29, %f28;
    cvt.rn.f16x2.f32 %r75, %f31, %f30;
    st.global.v4.b32 [%rd20+128], {%r60,%r61,%r62,%r63};
    st.global.v4.b32 [%rd20+144], {%r64,%r65,%r66,%r67};
    st.global.v4.b32 [%rd20+160], {%r68,%r69,%r70,%r71};
    st.global.v4.b32 [%rd20+176], {%r72,%r73,%r74,%r75};

    add.u32 %r40, %r10, 96;
    tcgen05.ld.sync.aligned.32x32b.x32.b32 {%f0,%f1,%f2,%f3,%f4,%f5,%f6,%f7,%f8,%f9,%f10,%f11,%f12,%f13,%f14,%f15,%f16,%f17,%f18,%f19,%f20,%f21,%f22,%f23,%f24,%f25,%f26,%f27,%f28,%f29,%f30,%f31}, [%r40];
    tcgen05.wait::ld.sync.aligned;
    cvt.rn.f16x2.f32 %r60, %f1, %f0;
    cvt.rn.f16x2.f32 %r61, %f3, %f2;
    cvt.rn.f16x2.f32 %r62, %f5, %f4;
    cvt.rn.f16x2.f32 %r63, %f7, %f6;
    cvt.rn.f16x2.f32 %r64, %f9, %f8;
    cvt.rn.f16x2.f32 %r65, %f11, %f10;
    cvt.rn.f16x2.f32 %r66, %f13, %f12;
    cvt.rn.f16x2.f32 %r67, %f15, %f14;
    cvt.rn.f16x2.f32 %r68, %f17, %f16;
    cvt.rn.f16x2.f32 %r69, %f19, %f18;
    cvt.rn.f16x2.f32 %r70, %f21, %f20;
    cvt.rn.f16x2.f32 %r71, %f23, %f22;
    cvt.rn.f16x2.f32 %r72, %f25, %f24;
    cvt.rn.f16x2.f32 %r73, %f27, %f26;
    cvt.rn.f16x2.f32 %r74, %f29, %f28;
    cvt.rn.f16x2.f32 %r75, %f31, %f30;
    st.global.v4.b32 [%rd20+192], {%r60,%r61,%r62,%r63};
    st.global.v4.b32 [%rd20+208], {%r64,%r65,%r66,%r67};
    st.global.v4.b32 [%rd20+224], {%r68,%r69,%r70,%r71};
    st.global.v4.b32 [%rd20+240], {%r72,%r73,%r74,%r75};

    bar.sync 0;
    @!%p1 bra SKIPD;
    tcgen05.dealloc.cta_group::1.sync.aligned.b32 %r10, 128;
SKIPD:
    ret;
}
)PTX";

static constexpr unsigned T5_SMEM = 69632;   // header + slack + 4x16KB buffers

// ---------------------------------------------------------------------------
// CUDA-side helpers
// ---------------------------------------------------------------------------
__device__ __forceinline__ uint32_t smem_u32(const void* p) {
    uint32_t a;
    asm("{ .reg .u64 t; cvta.to.shared.u64 t, %1; cvt.u32.u64 %0, t; }"
        : "=r"(a) : "l"(p));
    return a;
}
__device__ __forceinline__ void cp_async16(uint32_t dst, const void* src) {
    asm volatile("cp.async.cg.shared.global [%0], [%1], 16;"
                 :: "r"(dst), "l"(src) : "memory");
}
__device__ __forceinline__ void cp_commit() {
    asm volatile("cp.async.commit_group;" ::: "memory");
}
template <int N>
__device__ __forceinline__ void cp_wait() {
    asm volatile("cp.async.wait_group %0;" :: "n"(N) : "memory");
}
__device__ __forceinline__ void ldsm4(uint32_t* r, uint32_t addr) {
    asm volatile("ldmatrix.sync.aligned.m8n8.x4.shared.b16 {%0,%1,%2,%3}, [%4];"
                 : "=r"(r[0]), "=r"(r[1]), "=r"(r[2]), "=r"(r[3]) : "r"(addr));
}
__device__ __forceinline__ void ldsm4t(uint32_t* r, uint32_t addr) {
    asm volatile("ldmatrix.sync.aligned.m8n8.x4.trans.shared.b16 {%0,%1,%2,%3}, [%4];"
                 : "=r"(r[0]), "=r"(r[1]), "=r"(r[2]), "=r"(r[3]) : "r"(addr));
}
__device__ __forceinline__ void mma_f16(float (&c)[4],
                                        uint32_t a0, uint32_t a1, uint32_t a2, uint32_t a3,
                                        uint32_t b0, uint32_t b1) {
    asm volatile(
        "mma.sync.aligned.m16n8k16.row.col.f32.f16.f16.f32 "
        "{%0,%1,%2,%3}, {%4,%5,%6,%7}, {%8,%9}, {%0,%1,%2,%3};"
        : "+f"(c[0]), "+f"(c[1]), "+f"(c[2]), "+f"(c[3])
        : "r"(a0), "r"(a1), "r"(a2), "r"(a3), "r"(b0), "r"(b1));
}
__device__ __forceinline__ uint32_t cvt16x2(float hi, float lo) {
    uint32_t d;
    asm("cvt.rn.f16x2.f32 %0, %1, %2;" : "=r"(d) : "f"(hi), "f"(lo));
    return d;
}
__device__ __forceinline__ float ex2f(float x) {
    float r;
    asm("ex2.approx.ftz.f32 %0, %1;" : "=f"(r) : "f"(x));
    return r;
}

// ---------------------------------------------------------------------------
// pre/post-pass kernels
// ---------------------------------------------------------------------------
__global__ __launch_bounds__(256) void cvt_kernel(const float4* __restrict__ s,
                                                  uint2* __restrict__ d, int n4)
{
    int i = blockIdx.x * 256 + threadIdx.x;
    if (i < n4) {
        float4 v = s[i];
        d[i] = make_uint2(cvt16x2(v.y, v.x), cvt16x2(v.w, v.z));
    }
}

__global__ __launch_bounds__(256) void transcvt_kernel(const float* __restrict__ w,
                                                       __half* __restrict__ wt,
                                                       int K, int N)
{
    __shared__ float t[32][33];
    const int n0 = blockIdx.x * 32, k0 = blockIdx.y * 32;
    const int tx = threadIdx.x & 31, ty = threadIdx.x >> 5;
#pragma unroll
    for (int i = 0; i < 4; i++)
        t[ty + 8 * i][tx] = w[(size_t)(k0 + ty + 8 * i) * N + n0 + tx];
    __syncthreads();
#pragma unroll
    for (int i = 0; i < 4; i++)
        wt[(size_t)(n0 + ty + 8 * i) * K + k0 + tx] = __float2half_rn(t[tx][ty + 8 * i]);
}

__global__ __launch_bounds__(256) void bias_out_kernel(const __half2* __restrict__ h,
                                                       const float* __restrict__ bias,
                                                       float2* __restrict__ out, int n2)
{
    int i = blockIdx.x * 256 + threadIdx.x;
    if (i < n2) {
        __half2 v = h[i];
        int col = (i & (DIM / 2 - 1)) * 2;
        float2 o;
        o.x = __low2float(v) + bias[col];
        o.y = __high2float(v) + bias[col + 1];
        out[i] = o;
    }
}

// ---------------------------------------------------------------------------
// Fallback fp16 mma.sync GEMM (used only if JIT fails)
// ---------------------------------------------------------------------------
static constexpr int GEMM_SMEM = 6 * 16384;

template <bool OUT_F32>
__global__ __launch_bounds__(256)
void gemm_h(const __half* __restrict__ A, const __half* __restrict__ Bt,
            const float* __restrict__ bias, void* __restrict__ Cv,
            int M, int N, int K)
{
    extern __shared__ char sm[];
    const uint32_t sb = smem_u32(sm);
    const int tid = threadIdx.x, wid = tid >> 5, lane = tid & 31;
    const int wm = wid >> 2, wn = wid & 3;
    const int bRow = blockIdx.y * 128, bCol = blockIdx.x * 128;
    const int crow = tid >> 1, cc0 = (tid & 1) * 4;
    const __half* Arow = A + (size_t)(bRow + crow) * K;
    const __half* Brow = Bt + (size_t)(bCol + crow) * K;
    const int r8 = lane & 7;
    const int hA = (lane >> 3) & 1, gA = (lane >> 4) & 1;
    const int gB = (lane >> 3) & 1, hB = (lane >> 4) & 1;

    float acc[4][4][4];
#pragma unroll
    for (int i = 0; i < 4; i++)
#pragma unroll
        for (int j = 0; j < 4; j++)
#pragma unroll
            for (int v = 0; v < 4; v++) acc[i][j][v] = 0.f;

    auto stage = [&](int kc, int s) {
        const uint32_t ab = sb + (uint32_t)s * 16384u;
        const uint32_t bb = sb + 49152u + (uint32_t)s * 16384u;
        const uint32_t soff = (uint32_t)crow * 128u;
#pragma unroll
        for (int i = 0; i < 4; i++) {
            int c = cc0 + i;
            uint32_t sw = soff + 16u * (uint32_t)(c ^ (crow & 7));
            cp_async16(ab + sw, Arow + kc * 64 + c * 8);
            cp_async16(bb + sw, Brow + kc * 64 + c * 8);
        }
        cp_commit();
    };

    const int NC = K / 64;
    stage(0, 0); stage(1, 1);

#pragma unroll 1
    for (int kc = 0; kc < NC; kc++) {
        const int s = kc % 3;
        if (kc < NC - 1) cp_wait<1>(); else cp_wait<0>();
        __syncthreads();
        const uint32_t aB = sb + (uint32_t)s * 16384u;
        const uint32_t bB = sb + 49152u + (uint32_t)s * 16384u;
#pragma unroll
        for (int ks = 0; ks < 4; ks++) {
            uint32_t breg[2][4];
#pragma unroll
            for (int np = 0; np < 2; np++) {
                int nrow = wn * 32 + np * 16 + hB * 8 + r8;
                int ch = 2 * ks + gB;
                ldsm4(breg[np], bB + (uint32_t)nrow * 128u + 16u * (uint32_t)(ch ^ (nrow & 7)));
            }
#pragma unroll
            for (int mi = 0; mi < 4; mi++) {
                uint32_t areg[4];
                int arow = wm * 64 + mi * 16 + hA * 8 + r8;
                int ch = 2 * ks + gA;
                ldsm4(areg, aB + (uint32_t)arow * 128u + 16u * (uint32_t)(ch ^ (arow & 7)));
#pragma unroll
                for (int ni = 0; ni < 4; ni++) {
                    const uint32_t* br = breg[ni >> 1];
                    int off = (ni & 1) * 2;
                    mma_f16(acc[mi][ni], areg[0], areg[1], areg[2], areg[3], br[off], br[off + 1]);
                }
            }
        }
        if (kc + 2 < NC) stage(kc + 2, (kc + 2) % 3);
    }

    const int erow = lane >> 2, ecol = (lane & 3) * 2;
#pragma unroll
    for (int mi = 0; mi < 4; mi++)
#pragma unroll
        for (int ni = 0; ni < 4; ni++) {
            int col = bCol + wn * 32 + ni * 8 + ecol;
            int r0 = bRow + wm * 64 + mi * 16 + erow;
            if (OUT_F32) {
                float* C = (float*)Cv;
                float bx = bias[col], by = bias[col + 1];
                float2 v0 = { acc[mi][ni][0] + bx, acc[mi][ni][1] + by };
                float2 v1 = { acc[mi][ni][2] + bx, acc[mi][ni][3] + by };
                *(float2*)(C + (size_t)r0 * N + col) = v0;
                *(float2*)(C + (size_t)(r0 + 8) * N + col) = v1;
            } else {
                __half* C = (__half*)Cv;
                *(uint32_t*)(C + (size_t)r0 * N + col) = cvt16x2(acc[mi][ni][1], acc[mi][ni][0]);
                *(uint32_t*)(C + (size_t)(r0 + 8) * N + col) = cvt16x2(acc[mi][ni][3], acc[mi][ni][2]);
            }
        }
}

// ---------------------------------------------------------------------------
// Flash attention (unchanged)
// ---------------------------------------------------------------------------
__global__ __launch_bounds__(256, 2) void attn_fa(int b)
{
    const int h = blockIdx.y, tid = threadIdx.x;
    const int warp = tid >> 5, lane = tid & 31;

    __shared__ __align__(16) char sm[49152];
    const uint32_t base = smem_u32(sm);
    const __half* qkvB = g_qkv_h + (size_t)b * SEQ * (3 * DIM);

    const int rloc = warp * 16 + (lane >> 2);
    const int grow_lo = blockIdx.x * 128 + rloc;
    const __half* qp_lo = qkvB + (size_t)grow_lo * (3 * DIM) + h * HD;
    const __half* qp_hi = qp_lo + (size_t)8 * (3 * DIM);

    const __half2 csc2 = __float2half2_rn(CSC);
    uint32_t qf[4][4];
#pragma unroll
    for (int j = 0; j < 4; j++) {
        int k0 = j * 16 + 2 * (lane & 3);
        __half2 v;
        v = __hmul2(*(const __half2*)(qp_lo + k0),     csc2); qf[j][0] = *(uint32_t*)&v;
        v = __hmul2(*(const __half2*)(qp_hi + k0),     csc2); qf[j][1] = *(uint32_t*)&v;
        v = __hmul2(*(const __half2*)(qp_lo + k0 + 8), csc2); qf[j][2] = *(uint32_t*)&v;
        v = __hmul2(*(const __half2*)(qp_hi + k0 + 8), csc2); qf[j][3] = *(uint32_t*)&v;
    }

    float O[8][4];
#pragma unroll
    for (int i = 0; i < 8; i++)
#pragma unroll
        for (int c = 0; c < 4; c++) O[i][c] = 0.f;
    float l_lo = 0.f, l_hi = 0.f;
    float m_lo = -1e30f, m_hi = -1e30f;

    auto stage = [&](int j0, int s) {
#pragma unroll
        for (int i = 0; i < 2; i++) {
            int id = i * 256 + tid;
            int row = id >> 3, c = id & 7;
            const __half* kr = qkvB + (size_t)(j0 + row) * (3 * DIM) + DIM + h * HD + c * 8;
            uint32_t dst = base + (uint32_t)s * 8192u +
                           (uint32_t)row * 128u + 16u * (uint32_t)(c ^ (row & 7));
            cp_async16(dst, kr);
            cp_async16(dst + 24576u, kr + DIM);
        }
        cp_commit();
    };

    const int NT = SEQ / 64;
    stage(0, 0); stage(64, 1);

#pragma unroll 1
    for (int t = 0; t < NT; t++) {
        const int s = t % 3;
        if (t < NT - 1) cp_wait<1>(); else cp_wait<0>();
        __syncthreads();
        if (t + 2 < NT) stage((t + 2) * 64, (t + 2) % 3);

        const uint32_t kB = base + (uint32_t)s * 8192u;
        const uint32_t vB = kB + 24576u;

        float S[8][4];
#pragma unroll
        for (int nt = 0; nt < 8; nt++)
#pragma unroll
            for (int c = 0; c < 4; c++) S[nt][c] = 0.f;

#pragma unroll
        for (int blk = 0; blk < 2; blk++) {
            uint32_t bk[4][8];
#pragma unroll
            for (int i = 0; i < 4; i++) {
                int nt = blk * 4 + i;
#pragma unroll
                for (int ks2 = 0; ks2 < 2; ks2++) {
                    int mrow = 8 * nt + (lane & 7);
                    int chunk = ks2 * 4 + (lane >> 3);
                    ldsm4(&bk[i][ks2 * 4],
                          kB + (uint32_t)mrow * 128u + 16u * (uint32_t)(chunk ^ (mrow & 7)));
                }
            }
#pragma unroll
            for (int ks = 0; ks < 4; ks++)
#pragma unroll
                for (int i = 0; i < 4; i++)
                    mma_f16(S[blk * 4 + i], qf[ks][0], qf[ks][1], qf[ks][2], qf[ks][3],
                            bk[i][2 * ks], bk[i][2 * ks + 1]);
        }

        float tmax_lo = -1e30f, tmax_hi = -1e30f;
#pragma unroll
        for (int nt = 0; nt < 8; nt++) {
            tmax_lo = fmaxf(tmax_lo, fmaxf(S[nt][0], S[nt][1]));
            tmax_hi = fmaxf(tmax_hi, fmaxf(S[nt][2], S[nt][3]));
        }
        tmax_lo = fmaxf(tmax_lo, __shfl_xor_sync(0xffffffffu, tmax_lo, 1));
        tmax_lo = fmaxf(tmax_lo, __shfl_xor_sync(0xffffffffu, tmax_lo, 2));
        tmax_hi = fmaxf(tmax_hi, __shfl_xor_sync(0xffffffffu, tmax_hi, 1));
        tmax_hi = fmaxf(tmax_hi, __shfl_xor_sync(0xffffffffu, tmax_hi, 2));

        const float mn_lo = fmaxf(m_lo, tmax_lo);
        const float mn_hi = fmaxf(m_hi, tmax_hi);
        const float al = ex2f(m_lo - mn_lo);
        const float ah = ex2f(m_hi - mn_hi);
        m_lo = mn_lo; m_hi = mn_hi;

#pragma unroll
        for (int nt = 0; nt < 8; nt++) {
            O[nt][0] *= al; O[nt][1] *= al; O[nt][2] *= ah; O[nt][3] *= ah;
        }
        l_lo *= al; l_hi *= ah;

        uint32_t P[8][2];
#pragma unroll
        for (int nt = 0; nt < 8; nt++) {
            float p0 = ex2f(S[nt][0] - mn_lo);
            float p1 = ex2f(S[nt][1] - mn_lo);
            float p2 = ex2f(S[nt][2] - mn_hi);
            float p3 = ex2f(S[nt][3] - mn_hi);
            P[nt][0] = cvt16x2(p1, p0);
            P[nt][1] = cvt16x2(p3, p2);
            l_lo += p0 + p1;
            l_hi += p2 + p3;
        }

#pragma unroll
        for (int blk = 0; blk < 2; blk++) {
            uint32_t bv[4][8];
#pragma unroll
            for (int i = 0; i < 4; i++) {
                int nt = blk * 4 + i;
#pragma unroll
                for (int kp = 0; kp < 2; kp++) {
                    int mrow = 32 * kp + 8 * (lane >> 3) + (lane & 7);
                    ldsm4t(&bv[i][kp * 4],
                           vB + (uint32_t)mrow * 128u + 16u * (uint32_t)(nt ^ (mrow & 7)));
                }
            }
#pragma unroll
            for (int ks = 0; ks < 4; ks++)
#pragma unroll
                for (int i = 0; i < 4; i++)
                    mma_f16(O[blk * 4 + i],
                            P[2 * ks][0], P[2 * ks][1], P[2 * ks + 1][0], P[2 * ks + 1][1],
                            bv[i][2 * ks], bv[i][2 * ks + 1]);
        }
    }

    l_lo += __shfl_xor_sync(0xffffffffu, l_lo, 1);
    l_lo += __shfl_xor_sync(0xffffffffu, l_lo, 2);
    l_hi += __shfl_xor_sync(0xffffffffu, l_hi, 1);
    l_hi += __shfl_xor_sync(0xffffffffu, l_hi, 2);
    const float inv_lo = 1.f / l_lo;
    const float inv_hi = 1.f / l_hi;
    __half* orow_lo = g_attn_h + ((size_t)(b * SEQ) + grow_lo) * DIM + h * HD;
    __half* orow_hi = orow_lo + (size_t)8 * DIM;
#pragma unroll
    for (int nt = 0; nt < 8; nt++) {
        int col = nt * 8 + 2 * (lane & 3);
        *(uint32_t*)(orow_lo + col) = cvt16x2(O[nt][1] * inv_lo, O[nt][0] * inv_lo);
        *(uint32_t*)(orow_hi + col) = cvt16x2(O[nt][3] * inv_hi, O[nt][2] * inv_hi);
    }
}

// ---------------------------------------------------------------------------
// launcher — explicit streams; JIT + attribute setup on first call.
// ---------------------------------------------------------------------------
typedef CUresult (*PFN_cuModuleLoadDataEx)(CUmodule*, const void*, unsigned int,
                                           CUjit_option*, void**);
typedef CUresult (*PFN_cuModuleGetFunction)(CUfunction*, CUmodule, const char*);
typedef CUresult (*PFN_cuLaunchKernel)(CUfunction, unsigned, unsigned, unsigned,
                                       unsigned, unsigned, unsigned,
                                       unsigned, CUstream, void**, void**);
typedef CUresult (*PFN_cuFuncSetAttribute)(CUfunction, int, int);

static PFN_cuLaunchKernel s_culaunch = nullptr;
static CUfunction s_gemmt5 = nullptr;
static bool s_t5 = false;

static inline void t5_gemm(const __half* A, const __half* B, __half* C,
                           int N, int K, int M, cudaStream_t st)
{
    void* args[5] = { (void*)&A, (void*)&B, (void*)&C, (void*)&N, (void*)&K };
    s_culaunch(s_gemmt5, (unsigned)(N / 128), (unsigned)(M / 128), 1,
               128, 1, 1, T5_SMEM, (CUstream)st, args, nullptr);
}

extern "C" void kernel_launch(void* const* d_in, const int* in_sizes, int n_in,
                              void* d_out, int out_size)
{
    const float* x     = (const float*)d_in[0];
    const float* w_qkv = (const float*)d_in[1];
    const float* w_out = (const float*)d_in[2];
    const float* b_out = (const float*)d_in[3];
    float*       out   = (float*)d_out;

    __half *xh, *wqkvh, *wouth, *qkvh, *attnh;
    cudaGetSymbolAddress((void**)&xh,    g_x_h);
    cudaGetSymbolAddress((void**)&wqkvh, g_wqkv_h);
    cudaGetSymbolAddress((void**)&wouth, g_wout_h);
    cudaGetSymbolAddress((void**)&qkvh,  g_qkv_h);
    cudaGetSymbolAddress((void**)&attnh, g_attn_h);

    static bool inited = false;
    static cudaStream_t s0, s1, s2;
    static cudaEvent_t eFork, eDone;
    static cudaEvent_t eX[BATCH], eQ[BATCH], eA[BATCH];
    if (!inited) {
        cudaStreamCreateWithFlags(&s0, cudaStreamNonBlocking);
        cudaStreamCreateWithFlags(&s1, cudaStreamNonBlocking);
        cudaStreamCreateWithFlags(&s2, cudaStreamNonBlocking);
        cudaEventCreateWithFlags(&eFork, cudaEventDisableTiming);
        cudaEventCreateWithFlags(&eDone, cudaEventDisableTiming);
        for (int b = 0; b < BATCH; b++) {
            cudaEventCreateWithFlags(&eX[b], cudaEventDisableTiming);
            cudaEventCreateWithFlags(&eQ[b], cudaEventDisableTiming);
            cudaEventCreateWithFlags(&eA[b], cudaEventDisableTiming);
        }
        cudaFuncSetAttribute(gemm_h<false>,
                             cudaFuncAttributeMaxDynamicSharedMemorySize, GEMM_SMEM);
        cudaFuncSetAttribute(gemm_h<true>,
                             cudaFuncAttributeMaxDynamicSharedMemorySize, GEMM_SMEM);

        void* hcu = dlopen("libcuda.so.1", RTLD_NOW | RTLD_GLOBAL);
        if (hcu) {
            auto pLoad = (PFN_cuModuleLoadDataEx)dlsym(hcu, "cuModuleLoadDataEx");
            auto pGetF = (PFN_cuModuleGetFunction)dlsym(hcu, "cuModuleGetFunction");
            auto pSetA = (PFN_cuFuncSetAttribute)dlsym(hcu, "cuFuncSetAttribute");
            s_culaunch = (PFN_cuLaunchKernel)dlsym(hcu, "cuLaunchKernel");
            if (pLoad && pGetF && pSetA && s_culaunch) {
                static char elog[8192];
                CUjit_option opts[2] = { CU_JIT_ERROR_LOG_BUFFER,
                                         CU_JIT_ERROR_LOG_BUFFER_SIZE_BYTES };
                void* vals[2] = { (void*)elog, (void*)(size_t)sizeof(elog) };
                CUmodule mod;
                CUresult rc = pLoad(&mod, PTX_SRC, 2, opts, vals);
                if (rc == CUDA_SUCCESS &&
                    pGetF(&s_gemmt5, mod, "gemm_t5") == CUDA_SUCCESS &&
                    pSetA(s_gemmt5, /*MAX_DYNAMIC_SHARED_SIZE_BYTES*/8,
                          (int)T5_SMEM) == CUDA_SUCCESS) {
                    s_t5 = true;
                } else {
                    printf("T5 JIT failed rc=%d\n%s\n", (int)rc, elog);
                }
            }
        }
        inited = true;
    }

    const int BR = SEQ;
    const int n4b = BR * DIM / 4;

    cudaEventRecord(eFork, 0);
    cudaStreamWaitEvent(s0, eFork, 0);
    cudaStreamWaitEvent(s1, eFork, 0);
    cudaStreamWaitEvent(s2, eFork, 0);

    // s2: input converts + wout transpose
    for (int b = 0; b < BATCH; b++) {
        cvt_kernel<<<n4b / 256, 256, 0, s2>>>(
            (const float4*)(x + (size_t)b * BR * DIM),
            (uint2*)(xh + (size_t)b * BR * DIM), n4b);
        cudaEventRecord(eX[b], s2);
    }
    transcvt_kernel<<<dim3(DIM / 32, DIM / 32), 256, 0, s2>>>(w_out, wouth, DIM, DIM);

    // s0: qkv weight transpose + per-batch QKV GEMMs
    transcvt_kernel<<<dim3(3 * DIM / 32, DIM / 32), 256, 0, s0>>>(w_qkv, wqkvh, DIM, 3 * DIM);
    for (int b = 0; b < BATCH; b++) {
        cudaStreamWaitEvent(s0, eX[b], 0);
        if (s_t5)
            t5_gemm(xh + (size_t)b * BR * DIM, wqkvh,
                    qkvh + (size_t)b * BR * 3 * DIM, 3 * DIM, DIM, BR, s0);
        else
            gemm_h<false><<<dim3(3 * DIM / 128, BR / 128), 256, GEMM_SMEM, s0>>>(
                xh + (size_t)b * BR * DIM, wqkvh, nullptr,
                qkvh + (size_t)b * BR * 3 * DIM, BR, 3 * DIM, DIM);
        cudaEventRecord(eQ[b], s0);

        cudaStreamWaitEvent(s1, eQ[b], 0);
        attn_fa<<<dim3(SEQ / 128, NH, 1), 256, 0, s1>>>(b);
        cudaEventRecord(eA[b], s1);

        cudaStreamWaitEvent(s2, eA[b], 0);
        if (s_t5) {
            t5_gemm(attnh + (size_t)b * BR * DIM, wouth,
                    xh + (size_t)b * BR * DIM, DIM, DIM, BR, s2);
            int n2 = BR * DIM / 2;
            bias_out_kernel<<<(n2 + 255) / 256, 256, 0, s2>>>(
                (const __half2*)(xh + (size_t)b * BR * DIM), b_out,
                (float2*)(out + (size_t)b * BR * DIM), n2);
        } else {
            gemm_h<true><<<dim3(DIM / 128, BR / 128), 256, GEMM_SMEM, s2>>>(
                attnh + (size_t)b * BR * DIM, wouth, b_out,
                out + (size_t)b * BR * DIM, BR, DIM, DIM);
        }
    }

    cudaEventRecord(eDone, s2);
    cudaStreamWaitEvent(0, eDone, 0);
}